// round 1
// baseline (speedup 1.0000x reference)
#include <cuda_runtime.h>

// Murray/Wong-Wang single-area 2-unit integrator.
// B independent chains, T bins x steps_per_bin Euler substeps.
// Latency-chain-bound: ~60 cyc/substep * 8000 substeps.

#define A_P   270.0f
#define B_P   108.0f
#define C_P   0.154f
#define DT_P  0.001f
#define I0_P  0.334f
#define TAU_P 0.06f
#define GAM_P 0.641f

__device__ __forceinline__ float ex2_fast(float x) {
    float y; asm("ex2.approx.f32 %0, %1;" : "=f"(y) : "f"(x)); return y;
}
__device__ __forceinline__ float rcp_fast(float x) {
    float y; asm("rcp.approx.f32 %0, %1;" : "=f"(y) : "f"(x)); return y;
}

__global__ __launch_bounds__(64)
void murray_kernel(const float* __restrict__ input,   // [B, T, 2]
                   const float* __restrict__ h0,      // [1, B, 2]
                   const float* __restrict__ Jm,      // [2, 2]
                   const int*   __restrict__ spb_p,
                   float* __restrict__ out,           // states ++ rates ++ final
                   int Bsz, int T)
{
    const int b = blockIdx.x * blockDim.x + threadIdx.x;
    if (b >= Bsz) return;

    const int spb = *spb_p;
    const float sub_dt = DT_P / (float)spb;
    const float K1 = 1.0f - sub_dt / TAU_P;    // state decay multiplier
    const float K2 = sub_dt * GAM_P;           // gain on (1-s)*rate
    // Fold A into J and the additive term: act_j = s0*AJ0j + s1*AJ1j + (A*inp_j + A*I0 - B)
    const float aj00 = A_P * Jm[0];
    const float aj01 = A_P * Jm[1];
    const float aj10 = A_P * Jm[2];
    const float aj11 = A_P * Jm[3];
    const float cadd = A_P * I0_P - B_P;
    const float KE   = -C_P * 1.44269504088896340736f;  // exp(-C*act) = 2^(act*KE)
    const float invC = 1.0f / C_P;

    float s0 = h0[b * 2 + 0];
    float s1 = h0[b * 2 + 1];

    const size_t row = (size_t)b * (size_t)T * 2;
    const size_t BT2 = (size_t)Bsz * (size_t)T * 2;
    float* states = out + row;
    float* rateso = out + BT2 + row;
    float* finalo = out + 2 * BT2 + (size_t)b * 2;

    if (spb == 4 && (T & 3) == 0) {
        const float4* inp4 = (const float4*)(input + row);
        float4* st4 = (float4*)states;
        float4* rt4 = (float4*)rateso;
        const int ngroups = T >> 2;            // 4 bins per group = 32B I/O chunks

        float4 in0 = inp4[0];
        float4 in1 = inp4[1];

        for (int g = 0; g < ngroups; g++) {
            // unconditional prefetch of next group (clamped index, always valid)
            const int gn = (g + 1 < ngroups) ? (g + 1) : g;
            const float4 nin0 = inp4[gn * 2];
            const float4 nin1 = inp4[gn * 2 + 1];

            const float i0a[4] = {in0.x, in0.z, in1.x, in1.z};
            const float i1a[4] = {in0.y, in0.w, in1.y, in1.w};

            float sb[8], rb[8];

            #pragma unroll
            for (int q = 0; q < 4; q++) {
                const float c0 = fmaf(A_P, i0a[q], cadd);
                const float c1 = fmaf(A_P, i1a[q], cadd);
                float lr0 = 0.f, lr1 = 0.f;
                #pragma unroll
                for (int k = 0; k < 4; k++) {
                    const float act0 = fmaf(s0, aj00, fmaf(s1, aj10, c0));
                    const float act1 = fmaf(s0, aj01, fmaf(s1, aj11, c1));
                    const float e0 = ex2_fast(act0 * KE);
                    const float e1 = ex2_fast(act1 * KE);
                    const float d0 = 1.0f - e0;
                    const float d1 = 1.0f - e1;
                    float r0 = act0 * rcp_fast(d0);
                    float r1 = act1 * rcp_fast(d1);
                    r0 = (d0 == 0.0f) ? invC : r0;   // 0/0 limit = 1/C
                    r1 = (d1 == 0.0f) ? invC : r1;
                    const float w0 = fmaf(-K2, s0, K2);  // K2*(1-s0)
                    const float w1 = fmaf(-K2, s1, K2);
                    s0 = fmaf(w0, r0, s0 * K1);
                    s1 = fmaf(w1, r1, s1 * K1);
                    lr0 = r0; lr1 = r1;                  // keep last substep's rate
                }
                sb[2 * q]     = s0;  sb[2 * q + 1] = s1;
                rb[2 * q]     = lr0; rb[2 * q + 1] = lr1;
            }

            // 32B-per-array stores: full-sector efficiency
            st4[g * 2]     = make_float4(sb[0], sb[1], sb[2], sb[3]);
            st4[g * 2 + 1] = make_float4(sb[4], sb[5], sb[6], sb[7]);
            rt4[g * 2]     = make_float4(rb[0], rb[1], rb[2], rb[3]);
            rt4[g * 2 + 1] = make_float4(rb[4], rb[5], rb[6], rb[7]);

            in0 = nin0; in1 = nin1;
        }
    } else {
        // generic fallback (any spb / T)
        for (int t = 0; t < T; t++) {
            const float in0 = input[row + (size_t)t * 2 + 0];
            const float in1 = input[row + (size_t)t * 2 + 1];
            const float c0 = fmaf(A_P, in0, cadd);
            const float c1 = fmaf(A_P, in1, cadd);
            float lr0 = 0.f, lr1 = 0.f;
            for (int k = 0; k < spb; k++) {
                const float act0 = fmaf(s0, aj00, fmaf(s1, aj10, c0));
                const float act1 = fmaf(s0, aj01, fmaf(s1, aj11, c1));
                const float e0 = ex2_fast(act0 * KE);
                const float e1 = ex2_fast(act1 * KE);
                const float d0 = 1.0f - e0;
                const float d1 = 1.0f - e1;
                float r0 = act0 * rcp_fast(d0);
                float r1 = act1 * rcp_fast(d1);
                r0 = (d0 == 0.0f) ? invC : r0;
                r1 = (d1 == 0.0f) ? invC : r1;
                const float w0 = fmaf(-K2, s0, K2);
                const float w1 = fmaf(-K2, s1, K2);
                s0 = fmaf(w0, r0, s0 * K1);
                s1 = fmaf(w1, r1, s1 * K1);
                lr0 = r0; lr1 = r1;
            }
            states[(size_t)t * 2 + 0] = s0;
            states[(size_t)t * 2 + 1] = s1;
            rateso[(size_t)t * 2 + 0] = lr0;
            rateso[(size_t)t * 2 + 1] = lr1;
        }
    }

    finalo[0] = s0;
    finalo[1] = s1;
}

extern "C" void kernel_launch(void* const* d_in, const int* in_sizes, int n_in,
                              void* d_out, int out_size)
{
    const float* input = (const float*)d_in[0];   // [B, T, 2]
    const float* h0    = (const float*)d_in[1];   // [1, B, 2]
    const float* Jm    = (const float*)d_in[2];   // [2, 2]
    const int*   spb   = (const int*)d_in[3];

    const int Bsz = in_sizes[1] / 2;
    const int T   = in_sizes[0] / (Bsz * 2);

    const int threads = 64;
    const int blocks  = (Bsz + threads - 1) / threads;
    murray_kernel<<<blocks, threads>>>(input, h0, Jm, spb, (float*)d_out, Bsz, T);
}

// round 2
// speedup vs baseline: 1.4330x; 1.4330x over previous
#include <cuda_runtime.h>

// Murray/Wong-Wang single-area 2-unit integrator, latency-chain optimized.
// Recurrence tracked in u = KE*act so the per-substep critical path is only:
//   ex2(u) -> 1-e -> rcp -> fma -> fma   (~44 cyc)
// Everything else (s update, coefficients, I/O) hides in the MUFU shadow.

#define A_P   270.0f
#define B_P   108.0f
#define C_P   0.154f
#define DT_P  0.001f
#define I0_P  0.334f
#define TAU_P 0.06f
#define GAM_P 0.641f

__device__ __forceinline__ float ex2_fast(float x) {
    float y; asm("ex2.approx.f32 %0, %1;" : "=f"(y) : "f"(x)); return y;
}
__device__ __forceinline__ float rcp_fast(float x) {
    float y; asm("rcp.approx.f32 %0, %1;" : "=f"(y) : "f"(x)); return y;
}

__global__ __launch_bounds__(64)
void murray_kernel(const float* __restrict__ input,   // [B, T, 2]
                   const float* __restrict__ h0,      // [1, B, 2]
                   const float* __restrict__ Jm,      // [2, 2] row-major
                   const int*   __restrict__ spb_p,
                   float* __restrict__ out,           // states ++ rates ++ final
                   int Bsz, int T)
{
    const int b = blockIdx.x * blockDim.x + threadIdx.x;
    if (b >= Bsz) return;

    const int spb = *spb_p;
    const float sub_dt = DT_P / (float)spb;
    const float K1   = 1.0f - sub_dt / TAU_P;          // state decay
    const float K2   = sub_dt * GAM_P;                 // gain on (1-s)*rate
    const float L2E  = 1.44269504088896340736f;
    const float KE   = -C_P * L2E;                     // u = KE*act; exp(-C*act)=2^u
    const float invKE = 1.0f / KE;
    // act_j = s0*aj0j + s1*aj1j + c_j,  c_j = A*inp_j + cadd
    const float aj00 = A_P * Jm[0];
    const float aj01 = A_P * Jm[1];
    const float aj10 = A_P * Jm[2];
    const float aj11 = A_P * Jm[3];
    const float cadd = A_P * I0_P - B_P;
    const float KEA  = KE * A_P;                       // KC = KEA*inp + KEC
    const float KEC  = KE * cadd;
    const float kaj00 = KE * aj00, kaj10 = KE * aj10;
    const float kaj01 = KE * aj01, kaj11 = KE * aj11;
    const float OMK1 = 1.0f - K1;                      // = sub_dt/TAU

    float s0 = h0[b * 2 + 0];
    float s1 = h0[b * 2 + 1];

    const size_t row = (size_t)b * (size_t)T * 2;
    const size_t BT2 = (size_t)Bsz * (size_t)T * 2;
    float* states = out + row;
    float* rateso = out + BT2 + row;
    float* finalo = out + 2 * BT2 + (size_t)b * 2;

    if (spb == 4 && (T & 3) == 0) {
        const float4* inp4 = (const float4*)(input + row);
        float4* st4 = (float4*)states;
        float4* rt4 = (float4*)rateso;
        const int ngroups = T >> 2;   // 4 bins/group = 32B-per-array I/O

        float4 in0 = inp4[0];
        float4 in1 = inp4[1];

        // per-group bin constants KC_j[bin] = KE*c_j(bin); [4]=first bin of next grp
        float KCa[5], KCb[5];
        KCa[0] = fmaf(KEA, in0.x, KEC); KCb[0] = fmaf(KEA, in0.y, KEC);
        KCa[1] = fmaf(KEA, in0.z, KEC); KCb[1] = fmaf(KEA, in0.w, KEC);
        KCa[2] = fmaf(KEA, in1.x, KEC); KCb[2] = fmaf(KEA, in1.y, KEC);
        KCa[3] = fmaf(KEA, in1.z, KEC); KCb[3] = fmaf(KEA, in1.w, KEC);

        // initial u from h0 and first bin's input
        float u0 = fmaf(kaj00, s0, fmaf(kaj10, s1, KCa[0]));
        float u1 = fmaf(kaj01, s0, fmaf(kaj11, s1, KCb[0]));

        for (int g = 0; g < ngroups; g++) {
            const int gn = (g + 1 < ngroups) ? (g + 1) : g;   // clamped prefetch
            const float4 nin0 = inp4[gn * 2];
            const float4 nin1 = inp4[gn * 2 + 1];
            KCa[4] = fmaf(KEA, nin0.x, KEC);
            KCb[4] = fmaf(KEA, nin0.y, KEC);

            float sb[8], rb[8];

            #pragma unroll
            for (int q = 0; q < 4; q++) {
                const float KCc0 = KCa[q], KCc1 = KCb[q];
                const float NW0 = OMK1 * KCc0;               // within-bin base add
                const float NW1 = OMK1 * KCc1;
                const float NB0 = fmaf(-K1, KCc0, KCa[q + 1]); // bin-crossing add
                const float NB1 = fmaf(-K1, KCc1, KCb[q + 1]);
                float r0o = 0.f, r1o = 0.f;

                #pragma unroll
                for (int k = 0; k < 4; k++) {
                    // ---- critical path ----
                    const float e0 = ex2_fast(u0);
                    const float e1 = ex2_fast(u1);
                    const float d0 = 1.0f - e0;
                    const float d1 = 1.0f - e1;
                    const float p0 = rcp_fast(d0);
                    const float p1 = rcp_fast(d1);
                    // ---- shadow (depends only on u, s from before) ----
                    const float t0 = fmaf(-K2, s0, K2);      // K2*(1-s0)
                    const float t1 = fmaf(-K2, s1, K2);
                    const float w0 = t0 * u0;
                    const float w1 = t1 * u1;
                    const float N0 = (k == 3) ? NB0 : NW0;
                    const float N1 = (k == 3) ? NB1 : NW1;
                    const float base0 = fmaf(K1, u0, N0);
                    const float base1 = fmaf(K1, u1, N1);
                    const float vh0 = invKE * w0;
                    const float vh1 = invKE * w1;
                    const float ks0 = K1 * s0;
                    const float ks1 = K1 * s1;
                    // ---- chain tail: 2 fma levels after rcp ----
                    const float u0n = fmaf(aj00 * w0, p0, fmaf(aj10 * w1, p1, base0));
                    const float u1n = fmaf(aj11 * w1, p1, fmaf(aj01 * w0, p0, base1));
                    s0 = fmaf(vh0, p0, ks0);
                    s1 = fmaf(vh1, p1, ks1);
                    if (k == 3) {                            // last substep's rate
                        r0o = (u0 * invKE) * p0;
                        r1o = (u1 * invKE) * p1;
                    }
                    u0 = u0n; u1 = u1n;
                }
                sb[2 * q] = s0;  sb[2 * q + 1] = s1;
                rb[2 * q] = r0o; rb[2 * q + 1] = r1o;
            }

            st4[g * 2]     = make_float4(sb[0], sb[1], sb[2], sb[3]);
            st4[g * 2 + 1] = make_float4(sb[4], sb[5], sb[6], sb[7]);
            rt4[g * 2]     = make_float4(rb[0], rb[1], rb[2], rb[3]);
            rt4[g * 2 + 1] = make_float4(rb[4], rb[5], rb[6], rb[7]);

            in0 = nin0; in1 = nin1;
            KCa[0] = KCa[4]; KCb[0] = KCb[4];
            KCa[1] = fmaf(KEA, in0.z, KEC); KCb[1] = fmaf(KEA, in0.w, KEC);
            KCa[2] = fmaf(KEA, in1.x, KEC); KCb[2] = fmaf(KEA, in1.y, KEC);
            KCa[3] = fmaf(KEA, in1.z, KEC); KCb[3] = fmaf(KEA, in1.w, KEC);
        }
    } else {
        // generic fallback (any spb / T)
        const float invC = 1.0f / C_P;
        for (int t = 0; t < T; t++) {
            const float i0 = input[row + (size_t)t * 2 + 0];
            const float i1 = input[row + (size_t)t * 2 + 1];
            const float c0 = fmaf(A_P, i0, cadd);
            const float c1 = fmaf(A_P, i1, cadd);
            float lr0 = 0.f, lr1 = 0.f;
            for (int k = 0; k < spb; k++) {
                const float act0 = fmaf(s0, aj00, fmaf(s1, aj10, c0));
                const float act1 = fmaf(s0, aj01, fmaf(s1, aj11, c1));
                const float e0 = ex2_fast(act0 * KE);
                const float e1 = ex2_fast(act1 * KE);
                const float d0 = 1.0f - e0;
                const float d1 = 1.0f - e1;
                float r0 = act0 * rcp_fast(d0);
                float r1 = act1 * rcp_fast(d1);
                r0 = (d0 == 0.0f) ? invC : r0;
                r1 = (d1 == 0.0f) ? invC : r1;
                const float w0 = fmaf(-K2, s0, K2);
                const float w1 = fmaf(-K2, s1, K2);
                s0 = fmaf(w0, r0, s0 * K1);
                s1 = fmaf(w1, r1, s1 * K1);
                lr0 = r0; lr1 = r1;
            }
            states[(size_t)t * 2 + 0] = s0;
            states[(size_t)t * 2 + 1] = s1;
            rateso[(size_t)t * 2 + 0] = lr0;
            rateso[(size_t)t * 2 + 1] = lr1;
        }
    }

    finalo[0] = s0;
    finalo[1] = s1;
}

extern "C" void kernel_launch(void* const* d_in, const int* in_sizes, int n_in,
                              void* d_out, int out_size)
{
    const float* input = (const float*)d_in[0];   // [B, T, 2]
    const float* h0    = (const float*)d_in[1];   // [1, B, 2]
    const float* Jm    = (const float*)d_in[2];   // [2, 2]
    const int*   spb   = (const int*)d_in[3];

    const int Bsz = in_sizes[1] / 2;
    const int T   = in_sizes[0] / (Bsz * 2);

    const int threads = 64;
    const int blocks  = (Bsz + threads - 1) / threads;
    murray_kernel<<<blocks, threads>>>(input, h0, Jm, spb, (float*)d_out, Bsz, T);
}

// round 3
// speedup vs baseline: 1.6387x; 1.1435x over previous
#include <cuda_runtime.h>

// Murray/Wong-Wang 2-unit integrator, u-space recurrence (u = KE*act).
// Per-substep critical path: ex2(u) -> 1-e -> rcp -> fma -> fma.
// R3: spill-free variant — no indexed arrays, rolling scalars only,
// __launch_bounds__(64,1) to unlock the full register file.

#define A_P   270.0f
#define B_P   108.0f
#define C_P   0.154f
#define DT_P  0.001f
#define I0_P  0.334f
#define TAU_P 0.06f
#define GAM_P 0.641f

__device__ __forceinline__ float ex2_fast(float x) {
    float y; asm("ex2.approx.f32 %0, %1;" : "=f"(y) : "f"(x)); return y;
}
__device__ __forceinline__ float rcp_fast(float x) {
    float y; asm("rcp.approx.f32 %0, %1;" : "=f"(y) : "f"(x)); return y;
}

__global__ __launch_bounds__(64, 1)
void murray_kernel(const float* __restrict__ input,   // [B, T, 2]
                   const float* __restrict__ h0,      // [1, B, 2]
                   const float* __restrict__ Jm,      // [2, 2] row-major
                   const int*   __restrict__ spb_p,
                   float* __restrict__ out,           // states ++ rates ++ final
                   int Bsz, int T)
{
    const int b = blockIdx.x * blockDim.x + threadIdx.x;
    if (b >= Bsz) return;

    const int spb = *spb_p;
    const float sub_dt = DT_P / (float)spb;
    const float K1   = 1.0f - sub_dt / TAU_P;
    const float K2   = sub_dt * GAM_P;
    const float L2E  = 1.44269504088896340736f;
    const float KE   = -C_P * L2E;                 // u = KE*act
    const float invKE = 1.0f / KE;
    const float aj00 = A_P * Jm[0];
    const float aj01 = A_P * Jm[1];
    const float aj10 = A_P * Jm[2];
    const float aj11 = A_P * Jm[3];
    const float cadd = A_P * I0_P - B_P;
    const float KEA  = KE * A_P;
    const float KEC  = KE * cadd;
    const float kaj00 = KE * aj00, kaj10 = KE * aj10;
    const float kaj01 = KE * aj01, kaj11 = KE * aj11;
    const float OMK1 = 1.0f - K1;

    float s0 = h0[b * 2 + 0];
    float s1 = h0[b * 2 + 1];

    const size_t row = (size_t)b * (size_t)T * 2;
    const size_t BT2 = (size_t)Bsz * (size_t)T * 2;
    float* finalo = out + 2 * BT2 + (size_t)b * 2;

    if (spb == 4 && (T & 3) == 0) {
        const float4* inp4 = (const float4*)(input + row);
        float4* st4 = (float4*)(out + row);
        float4* rt4 = (float4*)(out + BT2 + row);
        const int ngroups = T >> 2;                // 4 bins/group, 32B I/O

        float4 cur0 = inp4[0];
        float4 cur1 = inp4[1];
        // current-bin constants
        float KC0 = fmaf(KEA, cur0.x, KEC);
        float KC1 = fmaf(KEA, cur0.y, KEC);
        // initial u from h0
        float u0 = fmaf(kaj00, s0, fmaf(kaj10, s1, KC0));
        float u1 = fmaf(kaj01, s0, fmaf(kaj11, s1, KC1));

        for (int g = 0; g < ngroups; g++) {
            const int gn = (g + 1 < ngroups) ? (g + 1) : g;   // clamped prefetch
            const float4 nxt0 = inp4[gn * 2];
            const float4 nxt1 = inp4[gn * 2 + 1];

            float4 sa, sb2, ra, rb2;   // store accumulators (2 bins each)

            #pragma unroll
            for (int q = 0; q < 4; q++) {
                // next bin's raw input pair (bin 3 -> first bin of next group)
                const float ni0 = (q == 0) ? cur0.z : (q == 1) ? cur1.x
                                 : (q == 2) ? cur1.z : nxt0.x;
                const float ni1 = (q == 0) ? cur0.w : (q == 1) ? cur1.y
                                 : (q == 2) ? cur1.w : nxt0.y;
                const float KC0n = fmaf(KEA, ni0, KEC);
                const float KC1n = fmaf(KEA, ni1, KEC);
                const float NW0 = OMK1 * KC0;
                const float NW1 = OMK1 * KC1;
                const float NB0 = fmaf(-K1, KC0, KC0n);   // bin-crossing add
                const float NB1 = fmaf(-K1, KC1, KC1n);
                float r0o, r1o;

                #pragma unroll
                for (int k = 0; k < 4; k++) {
                    // ---- critical path ----
                    const float e0 = ex2_fast(u0);
                    const float e1 = ex2_fast(u1);
                    const float d0 = 1.0f - e0;
                    const float d1 = 1.0f - e1;
                    const float p0 = rcp_fast(d0);
                    const float p1 = rcp_fast(d1);
                    // ---- shadow work (independent of p) ----
                    const float t0 = fmaf(-K2, s0, K2);
                    const float t1 = fmaf(-K2, s1, K2);
                    const float w0 = t0 * u0;
                    const float w1 = t1 * u1;
                    const float N0 = (k == 3) ? NB0 : NW0;
                    const float N1 = (k == 3) ? NB1 : NW1;
                    const float base0 = fmaf(K1, u0, N0);
                    const float base1 = fmaf(K1, u1, N1);
                    const float h00 = aj00 * w0;
                    const float h10 = aj10 * w1;
                    const float h01 = aj01 * w0;
                    const float h11 = aj11 * w1;
                    const float vh0 = invKE * w0;
                    const float vh1 = invKE * w1;
                    const float ks0 = K1 * s0;
                    const float ks1 = K1 * s1;
                    // ---- chain tail ----
                    const float u0n = fmaf(h00, p0, fmaf(h10, p1, base0));
                    const float u1n = fmaf(h11, p1, fmaf(h01, p0, base1));
                    s0 = fmaf(vh0, p0, ks0);
                    s1 = fmaf(vh1, p1, ks1);
                    if (k == 3) {
                        r0o = (u0 * invKE) * p0;
                        r1o = (u1 * invKE) * p1;
                    }
                    u0 = u0n; u1 = u1n;
                }

                if (q == 0)      { sa.x = s0; sa.y = s1; ra.x = r0o; ra.y = r1o; }
                else if (q == 1) { sa.z = s0; sa.w = s1; ra.z = r0o; ra.w = r1o; }
                else if (q == 2) { sb2.x = s0; sb2.y = s1; rb2.x = r0o; rb2.y = r1o; }
                else             { sb2.z = s0; sb2.w = s1; rb2.z = r0o; rb2.w = r1o; }

                KC0 = KC0n; KC1 = KC1n;
            }

            st4[g * 2]     = sa;
            st4[g * 2 + 1] = sb2;
            rt4[g * 2]     = ra;
            rt4[g * 2 + 1] = rb2;

            cur0 = nxt0; cur1 = nxt1;
        }
    } else {
        // generic fallback (any spb / T)
        float* states = out + row;
        float* rateso = out + BT2 + row;
        const float invC = 1.0f / C_P;
        for (int t = 0; t < T; t++) {
            const float i0 = input[row + (size_t)t * 2 + 0];
            const float i1 = input[row + (size_t)t * 2 + 1];
            const float c0 = fmaf(A_P, i0, cadd);
            const float c1 = fmaf(A_P, i1, cadd);
            float lr0 = 0.f, lr1 = 0.f;
            for (int k = 0; k < spb; k++) {
                const float act0 = fmaf(s0, aj00, fmaf(s1, aj10, c0));
                const float act1 = fmaf(s0, aj01, fmaf(s1, aj11, c1));
                const float e0 = ex2_fast(act0 * KE);
                const float e1 = ex2_fast(act1 * KE);
                const float d0 = 1.0f - e0;
                const float d1 = 1.0f - e1;
                float r0 = act0 * rcp_fast(d0);
                float r1 = act1 * rcp_fast(d1);
                r0 = (d0 == 0.0f) ? invC : r0;
                r1 = (d1 == 0.0f) ? invC : r1;
                const float w0 = fmaf(-K2, s0, K2);
                const float w1 = fmaf(-K2, s1, K2);
                s0 = fmaf(w0, r0, s0 * K1);
                s1 = fmaf(w1, r1, s1 * K1);
                lr0 = r0; lr1 = r1;
            }
            states[(size_t)t * 2 + 0] = s0;
            states[(size_t)t * 2 + 1] = s1;
            rateso[(size_t)t * 2 + 0] = lr0;
            rateso[(size_t)t * 2 + 1] = lr1;
        }
    }

    finalo[0] = s0;
    finalo[1] = s1;
}

extern "C" void kernel_launch(void* const* d_in, const int* in_sizes, int n_in,
                              void* d_out, int out_size)
{
    const float* input = (const float*)d_in[0];   // [B, T, 2]
    const float* h0    = (const float*)d_in[1];   // [1, B, 2]
    const float* Jm    = (const float*)d_in[2];   // [2, 2]
    const int*   spb   = (const int*)d_in[3];

    const int Bsz = in_sizes[1] / 2;
    const int T   = in_sizes[0] / (Bsz * 2);

    const int threads = 64;
    const int blocks  = (Bsz + threads - 1) / threads;
    murray_kernel<<<blocks, threads>>>(input, h0, Jm, spb, (float*)d_out, Bsz, T);
}

// round 4
// speedup vs baseline: 2.3951x; 1.4615x over previous
#include <cuda_runtime.h>

// Murray/Wong-Wang 2-unit integrator.
// Recurrence in (u = KE*act, a = K2*(1-s)) space.
// Per-substep critical path: ex2(u) -> 1-e -> rcp -> fma(p0 inner) -> fma(p1 outer)
// ~48 cycles; everything else scheduled into the MUFU shadow.

#define A_P   270.0f
#define B_P   108.0f
#define C_P   0.154f
#define DT_P  0.001f
#define I0_P  0.334f
#define TAU_P 0.06f
#define GAM_P 0.641f

__device__ __forceinline__ float ex2_fast(float x) {
    float y; asm("ex2.approx.ftz.f32 %0, %1;" : "=f"(y) : "f"(x)); return y;
}
__device__ __forceinline__ float rcp_fast(float x) {
    float y; asm("rcp.approx.ftz.f32 %0, %1;" : "=f"(y) : "f"(x)); return y;
}

__global__ __launch_bounds__(64, 1)
void murray_kernel(const float* __restrict__ input,   // [B, T, 2]
                   const float* __restrict__ h0,      // [1, B, 2]
                   const float* __restrict__ Jm,      // [2, 2] row-major
                   const int*   __restrict__ spb_p,
                   float* __restrict__ out,           // states ++ rates ++ final
                   int Bsz, int T)
{
    const int b = blockIdx.x * blockDim.x + threadIdx.x;
    if (b >= Bsz) return;

    const int spb = *spb_p;
    const float sub_dt = DT_P / (float)spb;
    const float K1    = 1.0f - sub_dt / TAU_P;
    const float K2    = sub_dt * GAM_P;
    const float L2E   = 1.44269504088896340736f;
    const float KE    = -C_P * L2E;                 // u = KE*act
    const float invKE = 1.0f / KE;
    const float aj00 = A_P * Jm[0];
    const float aj01 = A_P * Jm[1];
    const float aj10 = A_P * Jm[2];
    const float aj11 = A_P * Jm[3];
    const float cadd = A_P * I0_P - B_P;
    const float KEA  = KE * A_P;
    const float KEC  = KE * cadd;
    const float kaj00 = KE * aj00, kaj10 = KE * aj10;
    const float kaj01 = KE * aj01, kaj11 = KE * aj11;
    const float OMK1  = 1.0f - K1;
    const float CB    = K2 * OMK1;                  // a-update constant
    const float mKiv  = -K2 * invKE;                // m = mKiv * w
    const float invK2n = -1.0f / K2;                // s = fma(a, -1/K2, 1)

    float s0i = h0[b * 2 + 0];
    float s1i = h0[b * 2 + 1];
    float a0 = fmaf(-K2, s0i, K2);
    float a1 = fmaf(-K2, s1i, K2);

    const size_t row = (size_t)b * (size_t)T * 2;
    const size_t BT2 = (size_t)Bsz * (size_t)T * 2;
    float* finalo = out + 2 * BT2 + (size_t)b * 2;

    if (spb == 4 && (T & 3) == 0) {
        const float4* inp4 = (const float4*)(input + row);
        float4* st4 = (float4*)(out + row);
        float4* rt4 = (float4*)(out + BT2 + row);
        const int ngroups = T >> 2;

        float4 cur0 = inp4[0];
        float4 cur1 = inp4[1];
        float KC0 = fmaf(KEA, cur0.x, KEC);
        float KC1 = fmaf(KEA, cur0.y, KEC);
        float u0 = fmaf(kaj00, s0i, fmaf(kaj10, s1i, KC0));
        float u1 = fmaf(kaj01, s0i, fmaf(kaj11, s1i, KC1));

        for (int g = 0; g < ngroups; g++) {
            const int gn = (g + 1 < ngroups) ? (g + 1) : g;   // clamped prefetch
            const float4 nxt0 = inp4[gn * 2];
            const float4 nxt1 = inp4[gn * 2 + 1];

            float4 sa, sb2, ra, rb2;

            #pragma unroll
            for (int q = 0; q < 4; q++) {
                const float ni0 = (q == 0) ? cur0.z : (q == 1) ? cur1.x
                                 : (q == 2) ? cur1.z : nxt0.x;
                const float ni1 = (q == 0) ? cur0.w : (q == 1) ? cur1.y
                                 : (q == 2) ? cur1.w : nxt0.y;
                const float KC0n = fmaf(KEA, ni0, KEC);
                const float KC1n = fmaf(KEA, ni1, KEC);
                const float NW0 = OMK1 * KC0;
                const float NW1 = OMK1 * KC1;
                const float NB0 = fmaf(-K1, KC0, KC0n);
                const float NB1 = fmaf(-K1, KC1, KC1n);
                float r0o, r1o;

                #pragma unroll
                for (int k = 0; k < 4; k++) {
                    // ---- critical path ----
                    const float e0 = ex2_fast(u0);
                    const float e1 = ex2_fast(u1);
                    const float d0 = 1.0f - e0;
                    const float d1 = 1.0f - e1;
                    const float p0 = rcp_fast(d0);
                    const float p1 = rcp_fast(d1);
                    // ---- shadow (ready before p0/p1 return) ----
                    const float w0 = a0 * u0;
                    const float w1 = a1 * u1;
                    const float h00 = aj00 * w0;
                    const float h10 = aj10 * w1;
                    const float h01 = aj01 * w0;
                    const float h11 = aj11 * w1;
                    const float N0 = (k == 3) ? NB0 : NW0;
                    const float N1 = (k == 3) ? NB1 : NW1;
                    const float base0 = fmaf(K1, u0, N0);
                    const float base1 = fmaf(K1, u1, N1);
                    const float ab0 = fmaf(K1, a0, CB);
                    const float ab1 = fmaf(K1, a1, CB);
                    const float m0 = mKiv * w0;
                    const float m1 = mKiv * w1;
                    // ---- chain tail: p0 feeds INNER fma (p0 ready first) ----
                    const float u0n = fmaf(h10, p1, fmaf(h00, p0, base0));
                    const float u1n = fmaf(h11, p1, fmaf(h01, p0, base1));
                    a0 = fmaf(m0, p0, ab0);
                    a1 = fmaf(m1, p1, ab1);
                    if (k == 3) {
                        r0o = (invKE * u0) * p0;
                        r1o = (invKE * u1) * p1;
                    }
                    u0 = u0n; u1 = u1n;
                }

                const float s0o = fmaf(a0, invK2n, 1.0f);
                const float s1o = fmaf(a1, invK2n, 1.0f);
                if (q == 0)      { sa.x = s0o; sa.y = s1o; ra.x = r0o; ra.y = r1o; }
                else if (q == 1) { sa.z = s0o; sa.w = s1o; ra.z = r0o; ra.w = r1o; }
                else if (q == 2) { sb2.x = s0o; sb2.y = s1o; rb2.x = r0o; rb2.y = r1o; }
                else             { sb2.z = s0o; sb2.w = s1o; rb2.z = r0o; rb2.w = r1o; }

                KC0 = KC0n; KC1 = KC1n;
            }

            st4[g * 2]     = sa;
            st4[g * 2 + 1] = sb2;
            rt4[g * 2]     = ra;
            rt4[g * 2 + 1] = rb2;

            cur0 = nxt0; cur1 = nxt1;
        }
    } else {
        // generic fallback (any spb / T)
        float* states = out + row;
        float* rateso = out + BT2 + row;
        const float invC = 1.0f / C_P;
        float s0 = s0i, s1 = s1i;
        for (int t = 0; t < T; t++) {
            const float i0 = input[row + (size_t)t * 2 + 0];
            const float i1 = input[row + (size_t)t * 2 + 1];
            const float c0 = fmaf(A_P, i0, cadd);
            const float c1 = fmaf(A_P, i1, cadd);
            float lr0 = 0.f, lr1 = 0.f;
            for (int k = 0; k < spb; k++) {
                const float act0 = fmaf(s0, aj00, fmaf(s1, aj10, c0));
                const float act1 = fmaf(s0, aj01, fmaf(s1, aj11, c1));
                const float e0 = ex2_fast(act0 * KE);
                const float e1 = ex2_fast(act1 * KE);
                const float d0 = 1.0f - e0;
                const float d1 = 1.0f - e1;
                float r0 = act0 * rcp_fast(d0);
                float r1 = act1 * rcp_fast(d1);
                r0 = (d0 == 0.0f) ? invC : r0;
                r1 = (d1 == 0.0f) ? invC : r1;
                const float w0 = fmaf(-K2, s0, K2);
                const float w1 = fmaf(-K2, s1, K2);
                s0 = fmaf(w0, r0, s0 * K1);
                s1 = fmaf(w1, r1, s1 * K1);
                lr0 = r0; lr1 = r1;
            }
            states[(size_t)t * 2 + 0] = s0;
            states[(size_t)t * 2 + 1] = s1;
            rateso[(size_t)t * 2 + 0] = lr0;
            rateso[(size_t)t * 2 + 1] = lr1;
        }
        finalo[0] = s0;
        finalo[1] = s1;
        return;
    }

    finalo[0] = fmaf(a0, invK2n, 1.0f);
    finalo[1] = fmaf(a1, invK2n, 1.0f);
}

extern "C" void kernel_launch(void* const* d_in, const int* in_sizes, int n_in,
                              void* d_out, int out_size)
{
    const float* input = (const float*)d_in[0];   // [B, T, 2]
    const float* h0    = (const float*)d_in[1];   // [1, B, 2]
    const float* Jm    = (const float*)d_in[2];   // [2, 2]
    const int*   spb   = (const int*)d_in[3];

    const int Bsz = in_sizes[1] / 2;
    const int T   = in_sizes[0] / (Bsz * 2);

    const int threads = 64;
    const int blocks  = (Bsz + threads - 1) / threads;
    murray_kernel<<<blocks, threads>>>(input, h0, Jm, spb, (float*)d_out, Bsz, T);
}